// round 11
// baseline (speedup 1.0000x reference)
#include <cuda_runtime.h>
#include <cuda_bf16.h>
#include <math.h>

#define Bb   8
#define Nn   576
#define Dd   512
#define Mm   16
#define Hh   8
#define BN   (Bb*Nn)      // 4608
#define KTOP 51

typedef unsigned long long u64;
typedef unsigned int u32;

__device__ __forceinline__ u32 smem_u32(const void* p) {
    u32 a; asm("{ .reg .u64 t; cvta.to.shared.u64 t, %1; cvt.u32.u64 %0, t; }"
               : "=r"(a) : "l"(p));
    return a;
}

// ---- mma.sync helpers ----
__device__ __forceinline__ void ldsm4(u32* r, u32 addr) {
    asm volatile("ldmatrix.sync.aligned.m8n8.x4.shared.b16 {%0,%1,%2,%3}, [%4];"
                 : "=r"(r[0]), "=r"(r[1]), "=r"(r[2]), "=r"(r[3]) : "r"(addr));
}
__device__ __forceinline__ void ldsm4t(u32* r, u32 addr) {
    asm volatile("ldmatrix.sync.aligned.m8n8.x4.trans.shared.b16 {%0,%1,%2,%3}, [%4];"
                 : "=r"(r[0]), "=r"(r[1]), "=r"(r[2]), "=r"(r[3]) : "r"(addr));
}
__device__ __forceinline__ void mma16816(float* c, const u32* a, const u32* b) {
    asm volatile(
        "mma.sync.aligned.m16n8k16.row.col.f32.bf16.bf16.f32 "
        "{%0,%1,%2,%3}, {%4,%5,%6,%7}, {%8,%9}, {%0,%1,%2,%3};"
        : "+f"(c[0]), "+f"(c[1]), "+f"(c[2]), "+f"(c[3])
        : "r"(a[0]), "r"(a[1]), "r"(a[2]), "r"(a[3]), "r"(b[0]), "r"(b[1]));
}
__device__ __forceinline__ void cvt_split(float4 v, u32& hi0, u32& hi1, u32& lo0, u32& lo1) {
    __nv_bfloat162 h0 = __float22bfloat162_rn(make_float2(v.x, v.y));
    __nv_bfloat162 h1 = __float22bfloat162_rn(make_float2(v.z, v.w));
    float2 f0 = __bfloat1622float2(h0), f1 = __bfloat1622float2(h1);
    __nv_bfloat162 l0 = __float22bfloat162_rn(make_float2(v.x - f0.x, v.y - f0.y));
    __nv_bfloat162 l1 = __float22bfloat162_rn(make_float2(v.z - f1.x, v.w - f1.y));
    hi0 = *(u32*)&h0; hi1 = *(u32*)&h1; lo0 = *(u32*)&l0; lo1 = *(u32*)&l1;
}
__device__ __forceinline__ void cvt_split2(float x, float y, u32& hi, u32& lo) {
    __nv_bfloat162 h = __float22bfloat162_rn(make_float2(x, y));
    float2 f = __bfloat1622float2(h);
    __nv_bfloat162 l = __float22bfloat162_rn(make_float2(x - f.x, y - f.y));
    hi = *(u32*)&h; lo = *(u32*)&l;
}

// ---- cp.async ----
__device__ __forceinline__ void cpa16(u32 saddr, const void* g) {
    asm volatile("cp.async.cg.shared.global [%0], [%1], 16;" :: "r"(saddr), "l"(g));
}
#define CP_COMMIT() asm volatile("cp.async.commit_group;" ::: "memory")
#define CP_WAIT0()  asm volatile("cp.async.wait_group 0;" ::: "memory")
#define CP_WAIT1()  asm volatile("cp.async.wait_group 1;" ::: "memory")

// ---- scratch ----
__device__ __nv_bfloat16 g_qhi[BN * 3 * Dd];   // split qkv (Q pre-scaled 1/8)
__device__ __nv_bfloat16 g_qlo[BN * 3 * Dd];
__device__ __nv_bfloat16 g_Fhi[BN * Dd],  g_Flo[BN * Dd];
__device__ __nv_bfloat16 g_wqh[3*Dd*Dd],  g_wql[3*Dd*Dd];
__device__ __nv_bfloat16 g_woh[Dd*Dd],    g_wol[Dd*Dd];
__device__ __nv_bfloat16 g_w1h[Dd*Dd],    g_w1l[Dd*Dd];
__device__ __nv_bfloat16 g_athi[BN * Dd], g_atlo[BN * Dd];
__device__ __nv_bfloat16 g_fehi[BN * Dd], g_felo[BN * Dd];
__device__ float g_h   [BN * Dd];

// ============================================================
// One-launch fp32 -> bf16 hi/lo split over 4 tensors
// ============================================================
#define SEG0 589824
#define SEG1 (SEG0 + 196608)
#define SEG2 (SEG1 + 65536)
#define SEG3 (SEG2 + 65536)

__global__ __launch_bounds__(256) void split_all_kernel(
    const float* __restrict__ F,    const float* __restrict__ Wqkv,
    const float* __restrict__ Wout, const float* __restrict__ w1,
    __nv_bfloat16* __restrict__ Fhi, __nv_bfloat16* __restrict__ Flo,
    __nv_bfloat16* __restrict__ wqh, __nv_bfloat16* __restrict__ wql,
    __nv_bfloat16* __restrict__ woh, __nv_bfloat16* __restrict__ wol,
    __nv_bfloat16* __restrict__ w1h, __nv_bfloat16* __restrict__ w1l)
{
    int i = blockIdx.x * 256 + threadIdx.x;
    if (i >= SEG3) return;
    const float* src; __nv_bfloat16 *hi, *lo; int j;
    if (i < SEG0)      { src = F;    hi = Fhi; lo = Flo; j = i; }
    else if (i < SEG1) { src = Wqkv; hi = wqh; lo = wql; j = i - SEG0; }
    else if (i < SEG2) { src = Wout; hi = woh; lo = wol; j = i - SEG1; }
    else               { src = w1;   hi = w1h; lo = w1l; j = i - SEG2; }
    float4 v = reinterpret_cast<const float4*>(src)[j];
    u32 h0, h1, l0, l1;
    cvt_split(v, h0, h1, l0, l1);
    reinterpret_cast<uint2*>(hi)[j] = make_uint2(h0, h1);
    reinterpret_cast<uint2*>(lo)[j] = make_uint2(l0, l1);
}

// ============================================================
// Tensor-core SGEMM: pre-split bf16 hi/lo, cp.async 3-STAGE
// pipeline (3 buffers, wait_group 1). 512 threads, 128x128 tile,
// K-chunk 32, 80B rows (conflict-free).
// ============================================================
#define GROWB 80
#define GARR  (128 * GROWB)
#define GA_HI 0
#define GA_LO (1 * GARR)
#define GB_HI (2 * GARR)
#define GB_LO (3 * GARR)
#define GBUF  (4 * GARR)          // 40960
#define GEMM_SMEM (3 * GBUF)      // 122880

__global__ __launch_bounds__(512, 1) void sgemm_tc(
    const __nv_bfloat16* __restrict__ Ahi, const __nv_bfloat16* __restrict__ Alo,
    const __nv_bfloat16* __restrict__ Bhi, const __nv_bfloat16* __restrict__ Blo,
    const float* __restrict__ bias, const float* __restrict__ residual,
    float* __restrict__ C,
    __nv_bfloat16* __restrict__ Shi, __nv_bfloat16* __restrict__ Slo,
    int qsplit, int K, int N)
{
    extern __shared__ unsigned char smem[];
    const u32 sb = smem_u32(smem);

    const int tid = threadIdx.x;
    const int wid = tid >> 5, lid = tid & 31;
    const int rowBase = blockIdx.y * 128;
    const int colBase = blockIdx.x * 128;
    const int warp_m = (wid >> 2) * 32;
    const int warp_n = (wid & 3) * 32;

    const int lrow = tid >> 2;
    const int lc4  = tid & 3;
    const u32 so   = (u32)lrow * GROWB + (u32)lc4 * 16;
    const char* pAhi = (const char*)Ahi + ((size_t)(rowBase + lrow) * K) * 2 + lc4 * 16;
    const char* pAlo = (const char*)Alo + ((size_t)(rowBase + lrow) * K) * 2 + lc4 * 16;
    const char* pBhi = (const char*)Bhi + ((size_t)(colBase + lrow) * K) * 2 + lc4 * 16;
    const char* pBlo = (const char*)Blo + ((size_t)(colBase + lrow) * K) * 2 + lc4 * 16;

    const int a_row = warp_m + (lid & 15);
    const u32 a_kb  = (u32)(lid >> 4) * 16;
    const int b_n   = warp_n + (lid & 7) + ((lid >> 4) << 3);
    const u32 b_kb  = (u32)((lid >> 3) & 1) * 16;

    float acc[2][4][4];
    #pragma unroll
    for (int i = 0; i < 2; i++)
        #pragma unroll
        for (int j = 0; j < 4; j++)
            #pragma unroll
            for (int q = 0; q < 4; q++) acc[i][j][q] = 0.f;

    const int nChunk = K >> 5;

    // prefetch chunks 0 and 1
    #pragma unroll
    for (int p = 0; p < 2; p++) {
        u32 d = sb + (u32)p * GBUF + so;
        size_t kb = (size_t)p * 64;
        cpa16(d + GA_HI, pAhi + kb);
        cpa16(d + GA_LO, pAlo + kb);
        cpa16(d + GB_HI, pBhi + kb);
        cpa16(d + GB_LO, pBlo + kb);
        CP_COMMIT();
    }

    int buf = 0;
    for (int c = 0; c < nChunk; c++) {
        CP_WAIT1();              // oldest group (chunk c) complete
        __syncthreads();
        if (c + 2 < nChunk) {
            int nb = buf + 2; if (nb >= 3) nb -= 3;
            u32 d = sb + (u32)nb * GBUF + so;
            size_t kb = (size_t)(c + 2) * 64;
            cpa16(d + GA_HI, pAhi + kb);
            cpa16(d + GA_LO, pAlo + kb);
            cpa16(d + GB_HI, pBhi + kb);
            cpa16(d + GB_LO, pBlo + kb);
            CP_COMMIT();
        }

        const u32 bufo = (u32)buf * GBUF;
        #pragma unroll
        for (int ks = 0; ks < 2; ks++) {
            const u32 kso = (u32)ks * 32;
            u32 bhi[2][4], blo[2][4];
            #pragma unroll
            for (int np = 0; np < 2; np++) {
                u32 ba = sb + bufo + (u32)(b_n + np * 16) * GROWB + kso + b_kb;
                ldsm4(bhi[np], ba + GB_HI);
                ldsm4(blo[np], ba + GB_LO);
            }
            #pragma unroll
            for (int mt = 0; mt < 2; mt++) {
                u32 aa = sb + bufo + (u32)(a_row + mt * 16) * GROWB + kso + a_kb;
                u32 ahi[4], alo[4];
                ldsm4(ahi, aa + GA_HI);
                ldsm4(alo, aa + GA_LO);
                #pragma unroll
                for (int nt = 0; nt < 4; nt++) {
                    const u32* bh = &bhi[nt >> 1][(nt & 1) * 2];
                    const u32* bl = &blo[nt >> 1][(nt & 1) * 2];
                    mma16816(acc[mt][nt], ahi, bh);
                    mma16816(acc[mt][nt], ahi, bl);
                    mma16816(acc[mt][nt], alo, bh);
                }
            }
        }
        if (++buf == 3) buf = 0;
    }

    const int frow = lid >> 2;
    const int fcol = (lid & 3) * 2;
    #pragma unroll
    for (int mt = 0; mt < 2; mt++) {
        #pragma unroll
        for (int nt = 0; nt < 4; nt++) {
            int col = colBase + warp_n + nt * 8 + fcol;
            float2 bi = *reinterpret_cast<const float2*>(bias + col);
            #pragma unroll
            for (int half = 0; half < 2; half++) {
                int r = rowBase + warp_m + mt * 16 + frow + half * 8;
                float2 o;
                o.x = acc[mt][nt][half * 2 + 0] + bi.x;
                o.y = acc[mt][nt][half * 2 + 1] + bi.y;
                if (residual) {
                    float2 rv = *reinterpret_cast<const float2*>(residual + (size_t)r * N + col);
                    o.x += rv.x; o.y += rv.y;
                }
                if (C)
                    *reinterpret_cast<float2*>(C + (size_t)r * N + col) = o;
                if (Shi) {
                    float sc = (qsplit && col < 512) ? 0.125f : 1.0f;
                    u32 hb, lb;
                    cvt_split2(o.x * sc, o.y * sc, hb, lb);
                    *reinterpret_cast<u32*>(Shi + (size_t)r * N + col) = hb;
                    *reinterpret_cast<u32*>(Slo + (size_t)r * N + col) = lb;
                }
            }
        }
    }
}

// ============================================================
// Tensor-core flash attention (R10-passing, unchanged)
// ============================================================
#define ROWB 144
#define QT 96
#define KV_KHI 0
#define KV_KLO 9216
#define KV_VHI 18432
#define KV_VLO 27648
#define KVBUF  36864
#define AQ_HI  KVBUF
#define AQ_LO  (KVBUF + 13824)
#define ATTN_SMEM (2 * KVBUF)

__global__ __launch_bounds__(192) void attn_tc(
    const __nv_bfloat16* __restrict__ ghi, const __nv_bfloat16* __restrict__ glo,
    __nv_bfloat16* __restrict__ ohi, __nv_bfloat16* __restrict__ olo)
{
    extern __shared__ unsigned char smem[];
    const u32 sb = smem_u32(smem);

    const int tid = threadIdx.x;
    const int wid = tid >> 5, lid = tid & 31;
    const int bh = blockIdx.y;
    const int b = bh >> 3, h = bh & 7;
    const int q0 = blockIdx.x * QT;

    const __nv_bfloat16* qhi = ghi + (size_t)(b * Nn + q0) * 1536 + h * 64;
    const __nv_bfloat16* qlo = glo + (size_t)(b * Nn + q0) * 1536 + h * 64;
    const __nv_bfloat16* khi = ghi + (size_t)(b * Nn) * 1536 + 512  + h * 64;
    const __nv_bfloat16* klo = glo + (size_t)(b * Nn) * 1536 + 512  + h * 64;
    const __nv_bfloat16* vhi = ghi + (size_t)(b * Nn) * 1536 + 1024 + h * 64;
    const __nv_bfloat16* vlo = glo + (size_t)(b * Nn) * 1536 + 1024 + h * 64;

    for (int s = tid; s < 512; s += 192) {
        int row = s >> 3, c8 = s & 7;
        size_t go = (size_t)row * 1536 + c8 * 8;
        u32 so = sb + (u32)row * ROWB + (u32)c8 * 16;
        cpa16(so + KV_KHI, khi + go);
        cpa16(so + KV_KLO, klo + go);
        cpa16(so + KV_VHI, vhi + go);
        cpa16(so + KV_VLO, vlo + go);
    }
    #pragma unroll
    for (int it = 0; it < 4; it++) {
        int s = tid + it * 192;
        int row = s >> 3, c8 = s & 7;
        size_t go = (size_t)row * 1536 + c8 * 8;
        u32 so = sb + (u32)row * ROWB + (u32)c8 * 16;
        cpa16(so + AQ_HI, qhi + go);
        cpa16(so + AQ_LO, qlo + go);
    }
    CP_COMMIT();
    CP_WAIT0();
    __syncthreads();

    u32 qh[4][4], ql[4][4];
    {
        const int a_row = (wid << 4) + (lid & 15);
        const u32 a_kb = (u32)(lid >> 4) * 16;
        #pragma unroll
        for (int kt = 0; kt < 4; kt++) {
            u32 addr = sb + AQ_HI + (u32)a_row * ROWB + (u32)kt * 32 + a_kb;
            ldsm4(qh[kt], addr);
            ldsm4(ql[kt], addr + (AQ_LO - AQ_HI));
        }
    }
    __syncthreads();

    float m_lo = -1e30f, m_hi = -1e30f, l_lo = 0.f, l_hi = 0.f;
    float oacc[8][4];
    #pragma unroll
    for (int j = 0; j < 8; j++)
        #pragma unroll
        for (int q = 0; q < 4; q++) oacc[j][q] = 0.f;

    const int kb_row = (lid & 7) + ((lid >> 4) << 3);
    const u32 kb_kb  = (u32)((lid >> 3) & 1) * 16;
    const int vb_key = (lid & 7) + (((lid >> 3) & 1) << 3);
    const u32 vb_db  = (u32)(lid >> 4) * 16;

    const int nChunk = Nn / 64;
    for (int c = 0; c < nChunk; c++) {
        if (c + 1 < nChunk) {
            const u32 nb = sb + (u32)((c + 1) & 1) * KVBUF;
            const int kc1 = (c + 1) * 64;
            for (int s = tid; s < 512; s += 192) {
                int row = s >> 3, c8 = s & 7;
                size_t go = (size_t)(kc1 + row) * 1536 + c8 * 8;
                u32 so = nb + (u32)row * ROWB + (u32)c8 * 16;
                cpa16(so + KV_KHI, khi + go);
                cpa16(so + KV_KLO, klo + go);
                cpa16(so + KV_VHI, vhi + go);
                cpa16(so + KV_VLO, vlo + go);
            }
        }
        CP_COMMIT();

        const u32 bufb = sb + (u32)(c & 1) * KVBUF;

        float sacc[8][4];
        #pragma unroll
        for (int j = 0; j < 8; j++)
            #pragma unroll
            for (int q = 0; q < 4; q++) sacc[j][q] = 0.f;

        #pragma unroll
        for (int kt = 0; kt < 4; kt++) {
            #pragma unroll
            for (int ng = 0; ng < 4; ng++) {
                u32 ka = bufb + KV_KHI + (u32)(ng * 16 + kb_row) * ROWB + (u32)kt * 32 + kb_kb;
                u32 kh[4], kl[4];
                ldsm4(kh, ka);
                ldsm4(kl, ka + (KV_KLO - KV_KHI));
                #pragma unroll
                for (int half = 0; half < 2; half++) {
                    float* s = sacc[2 * ng + half];
                    const u32* bhp = &kh[half * 2];
                    const u32* blp = &kl[half * 2];
                    mma16816(s, qh[kt], bhp);
                    mma16816(s, qh[kt], blp);
                    mma16816(s, ql[kt], bhp);
                }
            }
        }

        float mx_lo = -1e30f, mx_hi = -1e30f;
        #pragma unroll
        for (int j = 0; j < 8; j++) {
            mx_lo = fmaxf(mx_lo, fmaxf(sacc[j][0], sacc[j][1]));
            mx_hi = fmaxf(mx_hi, fmaxf(sacc[j][2], sacc[j][3]));
        }
        #pragma unroll
        for (int o = 1; o <= 2; o <<= 1) {
            mx_lo = fmaxf(mx_lo, __shfl_xor_sync(0xffffffffu, mx_lo, o));
            mx_hi = fmaxf(mx_hi, __shfl_xor_sync(0xffffffffu, mx_hi, o));
        }
        float mn_lo = fmaxf(m_lo, mx_lo), mn_hi = fmaxf(m_hi, mx_hi);
        float corr_lo = __expf(m_lo - mn_lo), corr_hi = __expf(m_hi - mn_hi);
        float rs_lo = 0.f, rs_hi = 0.f;
        #pragma unroll
        for (int j = 0; j < 8; j++) {
            sacc[j][0] = __expf(sacc[j][0] - mn_lo);
            sacc[j][1] = __expf(sacc[j][1] - mn_lo);
            sacc[j][2] = __expf(sacc[j][2] - mn_hi);
            sacc[j][3] = __expf(sacc[j][3] - mn_hi);
            rs_lo += sacc[j][0] + sacc[j][1];
            rs_hi += sacc[j][2] + sacc[j][3];
        }
        #pragma unroll
        for (int o = 1; o <= 2; o <<= 1) {
            rs_lo += __shfl_xor_sync(0xffffffffu, rs_lo, o);
            rs_hi += __shfl_xor_sync(0xffffffffu, rs_hi, o);
        }
        l_lo = l_lo * corr_lo + rs_lo;
        l_hi = l_hi * corr_hi + rs_hi;
        m_lo = mn_lo; m_hi = mn_hi;
        #pragma unroll
        for (int j = 0; j < 8; j++) {
            oacc[j][0] *= corr_lo; oacc[j][1] *= corr_lo;
            oacc[j][2] *= corr_hi; oacc[j][3] *= corr_hi;
        }

        #pragma unroll
        for (int kt = 0; kt < 4; kt++) {
            const int j0 = 2 * kt, j1 = 2 * kt + 1;
            u32 aph[4], apl[4];
            cvt_split2(sacc[j0][0], sacc[j0][1], aph[0], apl[0]);
            cvt_split2(sacc[j0][2], sacc[j0][3], aph[1], apl[1]);
            cvt_split2(sacc[j1][0], sacc[j1][1], aph[2], apl[2]);
            cvt_split2(sacc[j1][2], sacc[j1][3], aph[3], apl[3]);
            #pragma unroll
            for (int ng = 0; ng < 4; ng++) {
                u32 va = bufb + KV_VHI + (u32)(kt * 16 + vb_key) * ROWB + (u32)ng * 32 + vb_db;
                u32 vh[4], vl[4];
                ldsm4t(vh, va);
                ldsm4t(vl, va + (KV_VLO - KV_VHI));
                #pragma unroll
                for (int half = 0; half < 2; half++) {
                    float* oa = oacc[2 * ng + half];
                    const u32* bhp = &vh[half * 2];
                    const u32* blp = &vl[half * 2];
                    mma16816(oa, aph, bhp);
                    mma16816(oa, aph, blp);
                    mma16816(oa, apl, bhp);
                }
            }
        }

        CP_WAIT0();
        __syncthreads();
    }

    const float inv_lo = 1.f / l_lo, inv_hi = 1.f / l_hi;
    const int r_lo = q0 + (wid << 4) + (lid >> 2);
    const int cb = h * 64 + (lid & 3) * 2;
    #pragma unroll
    for (int j = 0; j < 8; j++) {
        int col = cb + j * 8;
        u32 hb, lb;
        cvt_split2(oacc[j][0] * inv_lo, oacc[j][1] * inv_lo, hb, lb);
        *reinterpret_cast<u32*>(ohi + (size_t)(b * Nn + r_lo) * Dd + col) = hb;
        *reinterpret_cast<u32*>(olo + (size_t)(b * Nn + r_lo) * Dd + col) = lb;
        cvt_split2(oacc[j][2] * inv_hi, oacc[j][3] * inv_hi, hb, lb);
        *reinterpret_cast<u32*>(ohi + (size_t)(b * Nn + r_lo + 8) * Dd + col) = hb;
        *reinterpret_cast<u32*>(olo + (size_t)(b * Nn + r_lo + 8) * Dd + col) = lb;
    }
}

// ============================================================
// FUSED: LayerNorm -> GELU -> comp -> outer -> top-51 -> write
// (R10-passing, unchanged)
// ============================================================
__global__ __launch_bounds__(512) void ln_outer_topk_kernel(
    const float* __restrict__ hsrc,
    const float* __restrict__ ln_g, const float* __restrict__ ln_b,
    const float* __restrict__ w2,  const float* __restrict__ b2,
    const float* __restrict__ F, const float* __restrict__ templates,
    float* __restrict__ out)
{
    __shared__ float s[512];
    __shared__ float Frow[512];
    __shared__ float red[32];
    __shared__ float cs[16];
    __shared__ float Qout[512 * 17];

    const int row = blockIdx.x;
    const int tid = threadIdx.x;
    const int m = tid >> 5, lid = tid & 31;

    float x = hsrc[(size_t)row * 512 + tid];
    s[tid] = x;
    Frow[tid] = F[(size_t)row * 512 + tid];

    float sum = x, sq = x * x;
    #pragma unroll
    for (int o = 16; o >= 1; o >>= 1) {
        sum += __shfl_xor_sync(0xffffffffu, sum, o);
        sq  += __shfl_xor_sync(0xffffffffu, sq,  o);
    }
    if (lid == 0) { red[m] = sum; red[m + 16] = sq; }
    __syncthreads();
    if (tid == 0) {
        float S = 0.f, Q = 0.f;
        #pragma unroll
        for (int i = 0; i < 16; i++) { S += red[i]; Q += red[i + 16]; }
        red[0] = S * (1.f / 512.f);
        red[16] = Q * (1.f / 512.f);
    }
    __syncthreads();
    const float mean = red[0];
    const float rstd = rsqrtf(red[16] - mean * mean + 1e-5f);

    float g = (x - mean) * rstd * ln_g[tid] + ln_b[tid];
    g = 0.5f * g * (1.f + erff(g * 0.70710678118f));
    __syncthreads();
    s[tid] = g;
    __syncthreads();

    {
        float p = 0.f;
        const float* wrow = w2 + m * 512;
        #pragma unroll
        for (int i = 0; i < 16; i++) {
            int e = lid + 32 * i;
            p += s[e] * wrow[e];
        }
        #pragma unroll
        for (int o = 16; o >= 1; o >>= 1)
            p += __shfl_xor_sync(0xffffffffu, p, o);
        if (lid == 0) cs[m] = p + b2[m];
    }
    __syncthreads();

    const float c = cs[m];
    float    qv[16];
    unsigned key[16];
    unsigned mx = 0;
    #pragma unroll
    for (int i = 0; i < 16; i++) {
        int d = lid + 32 * i;
        float q = Frow[d] * templates[m * 512 + d] * c;
        qv[i]  = q;
        key[i] = __float_as_uint(fabsf(q));
        mx = max(mx, key[i]);
    }
    #pragma unroll
    for (int o = 16; o >= 1; o >>= 1)
        mx = max(mx, __shfl_xor_sync(0xffffffffu, mx, o));

    unsigned prefix = 0;
    int bit = 31 - __clz(mx | 1u);
    for (; bit >= 0; bit--) {
        unsigned test = prefix | (1u << bit);
        int cnt = 0;
        #pragma unroll
        for (int i = 0; i < 16; i++) cnt += (key[i] >= test);
        cnt = __reduce_add_sync(0xffffffffu, cnt);
        if (cnt >= KTOP) {
            prefix = test;
            if (cnt == KTOP) break;
        }
    }

    #pragma unroll
    for (int i = 0; i < 16; i++) {
        int d = lid + 32 * i;
        Qout[d * 17 + m] = (key[i] >= prefix) ? qv[i] : 0.f;
    }
    __syncthreads();

    float* ob = out + (size_t)row * (512 * 16);
    #pragma unroll
    for (int i = 0; i < 16; i++) {
        int e = tid + 512 * i;
        ob[e] = Qout[(e >> 4) * 17 + (e & 15)];
    }
}

// ============================================================
extern "C" void kernel_launch(void* const* d_in, const int* in_sizes, int n_in,
                              void* d_out, int out_size) {
    const float* F    = (const float*)d_in[0];
    const float* Wqkv = (const float*)d_in[1];
    const float* bqkv = (const float*)d_in[2];
    const float* Wout = (const float*)d_in[3];
    const float* bout = (const float*)d_in[4];
    const float* w1   = (const float*)d_in[5];
    const float* b1   = (const float*)d_in[6];
    const float* lng  = (const float*)d_in[7];
    const float* lnb  = (const float*)d_in[8];
    const float* w2   = (const float*)d_in[9];
    const float* b2   = (const float*)d_in[10];
    const float* tmpl = (const float*)d_in[11];
    float* out = (float*)d_out;

    __nv_bfloat16 *qhi, *qlo, *Fhi, *Flo, *wqh, *wql, *woh, *wol, *w1h, *w1l;
    __nv_bfloat16 *athi, *atlo, *fehi, *felo;
    float *hbuf;
    cudaGetSymbolAddress((void**)&qhi,  g_qhi);
    cudaGetSymbolAddress((void**)&qlo,  g_qlo);
    cudaGetSymbolAddress((void**)&Fhi,  g_Fhi);
    cudaGetSymbolAddress((void**)&Flo,  g_Flo);
    cudaGetSymbolAddress((void**)&wqh,  g_wqh);
    cudaGetSymbolAddress((void**)&wql,  g_wql);
    cudaGetSymbolAddress((void**)&woh,  g_woh);
    cudaGetSymbolAddress((void**)&wol,  g_wol);
    cudaGetSymbolAddress((void**)&w1h,  g_w1h);
    cudaGetSymbolAddress((void**)&w1l,  g_w1l);
    cudaGetSymbolAddress((void**)&athi, g_athi);
    cudaGetSymbolAddress((void**)&atlo, g_atlo);
    cudaGetSymbolAddress((void**)&fehi, g_fehi);
    cudaGetSymbolAddress((void**)&felo, g_felo);
    cudaGetSymbolAddress((void**)&hbuf, g_h);

    cudaFuncSetAttribute(sgemm_tc, cudaFuncAttributeMaxDynamicSharedMemorySize,
                         GEMM_SMEM);
    cudaFuncSetAttribute(attn_tc, cudaFuncAttributeMaxDynamicSharedMemorySize,
                         ATTN_SMEM);

    split_all_kernel<<<(SEG3 + 255) / 256, 256>>>(
        F, Wqkv, Wout, w1, Fhi, Flo, wqh, wql, woh, wol, w1h, w1l);

    sgemm_tc<<<dim3(1536 / 128, BN / 128), 512, GEMM_SMEM>>>(
        Fhi, Flo, wqh, wql, bqkv, nullptr, nullptr, qhi, qlo, 1, 512, 1536);
    attn_tc<<<dim3(Nn / QT, Bb * Hh), 192, ATTN_SMEM>>>(qhi, qlo, athi, atlo);
    sgemm_tc<<<dim3(512 / 128, BN / 128), 512, GEMM_SMEM>>>(
        athi, atlo, woh, wol, bout, F, nullptr, fehi, felo, 0, 512, 512);
    sgemm_tc<<<dim3(512 / 128, BN / 128), 512, GEMM_SMEM>>>(
        fehi, felo, w1h, w1l, b1, nullptr, hbuf, nullptr, nullptr, 0, 512, 512);
    ln_outer_topk_kernel<<<BN, 512>>>(hbuf, lng, lnb, w2, b2, F, tmpl, out);
}

// round 12
// speedup vs baseline: 1.1682x; 1.1682x over previous
#include <cuda_runtime.h>
#include <cuda_fp16.h>
#include <math.h>

#define Bb   8
#define Nn   576
#define Dd   512
#define Mm   16
#define Hh   8
#define BN   (Bb*Nn)      // 4608
#define KTOP 51

typedef unsigned long long u64;
typedef unsigned int u32;

__device__ __forceinline__ u32 smem_u32(const void* p) {
    u32 a; asm("{ .reg .u64 t; cvta.to.shared.u64 t, %1; cvt.u32.u64 %0, t; }"
               : "=r"(a) : "l"(p));
    return a;
}

// ---- mma.sync helpers (fp16 in, fp32 acc) ----
__device__ __forceinline__ void ldsm4(u32* r, u32 addr) {
    asm volatile("ldmatrix.sync.aligned.m8n8.x4.shared.b16 {%0,%1,%2,%3}, [%4];"
                 : "=r"(r[0]), "=r"(r[1]), "=r"(r[2]), "=r"(r[3]) : "r"(addr));
}
__device__ __forceinline__ void ldsm4t(u32* r, u32 addr) {
    asm volatile("ldmatrix.sync.aligned.m8n8.x4.trans.shared.b16 {%0,%1,%2,%3}, [%4];"
                 : "=r"(r[0]), "=r"(r[1]), "=r"(r[2]), "=r"(r[3]) : "r"(addr));
}
__device__ __forceinline__ void mma16816(float* c, const u32* a, const u32* b) {
    asm volatile(
        "mma.sync.aligned.m16n8k16.row.col.f32.f16.f16.f32 "
        "{%0,%1,%2,%3}, {%4,%5,%6,%7}, {%8,%9}, {%0,%1,%2,%3};"
        : "+f"(c[0]), "+f"(c[1]), "+f"(c[2]), "+f"(c[3])
        : "r"(a[0]), "r"(a[1]), "r"(a[2]), "r"(a[3]), "r"(b[0]), "r"(b[1]));
}

// ---- fp16 conversion helpers ----
__device__ __forceinline__ u32 h2pack(float x, float y) {
    __half2 h = __floats2half2_rn(x, y);
    return *(u32*)&h;
}
__device__ __forceinline__ void h2_split(float x, float y, u32& hi, u32& lo) {
    __half2 h = __floats2half2_rn(x, y);
    float2 f = __half22float2(h);
    __half2 l = __floats2half2_rn(x - f.x, y - f.y);
    hi = *(u32*)&h; lo = *(u32*)&l;
}
__device__ __forceinline__ void h4_split(float4 v, u32& hi0, u32& hi1, u32& lo0, u32& lo1) {
    h2_split(v.x, v.y, hi0, lo0);
    h2_split(v.z, v.w, hi1, lo1);
}

// ---- cp.async ----
__device__ __forceinline__ void cpa16(u32 saddr, const void* g) {
    asm volatile("cp.async.cg.shared.global [%0], [%1], 16;" :: "r"(saddr), "l"(g));
}
#define CP_COMMIT() asm volatile("cp.async.commit_group;" ::: "memory")
#define CP_WAIT0()  asm volatile("cp.async.wait_group 0;" ::: "memory")

// ---- scratch (fp16) ----
__device__ __half g_qhi[BN * 3 * Dd];   // qkv hi (Q pre-scaled 1/8)
__device__ __half g_qlo[BN * 3 * Dd];   // qkv lo (only K,V parts consumed)
__device__ __half g_Fhi[BN * Dd];
__device__ __half g_wqh[3*Dd*Dd], g_wql[3*Dd*Dd];
__device__ __half g_woh[Dd*Dd],   g_wol[Dd*Dd];
__device__ __half g_w1h[Dd*Dd],   g_w1l[Dd*Dd];
__device__ __half g_athi[BN * Dd];                 // attention out (single)
__device__ __half g_fehi[BN * Dd], g_felo[BN * Dd];
__device__ float g_h[BN * Dd];

// ============================================================
// One-launch fp32 -> fp16 split: F (hi only), Wqkv/Wout/w1 (hi+lo)
// ============================================================
#define SEG0 589824
#define SEG1 (SEG0 + 196608)
#define SEG2 (SEG1 + 65536)
#define SEG3 (SEG2 + 65536)

__global__ __launch_bounds__(256) void split_all_kernel(
    const float* __restrict__ F,    const float* __restrict__ Wqkv,
    const float* __restrict__ Wout, const float* __restrict__ w1,
    __half* __restrict__ Fhi,
    __half* __restrict__ wqh, __half* __restrict__ wql,
    __half* __restrict__ woh, __half* __restrict__ wol,
    __half* __restrict__ w1h, __half* __restrict__ w1l)
{
    int i = blockIdx.x * 256 + threadIdx.x;
    if (i >= SEG3) return;
    u32 h0, h1, l0, l1;
    if (i < SEG0) {
        float4 v = reinterpret_cast<const float4*>(F)[i];
        h4_split(v, h0, h1, l0, l1);
        reinterpret_cast<uint2*>(Fhi)[i] = make_uint2(h0, h1);
        return;
    }
    const float* src; __half *hi, *lo; int j;
    if (i < SEG1)      { src = Wqkv; hi = wqh; lo = wql; j = i - SEG0; }
    else if (i < SEG2) { src = Wout; hi = woh; lo = wol; j = i - SEG1; }
    else               { src = w1;   hi = w1h; lo = w1l; j = i - SEG2; }
    float4 v = reinterpret_cast<const float4*>(src)[j];
    h4_split(v, h0, h1, l0, l1);
    reinterpret_cast<uint2*>(hi)[j] = make_uint2(h0, h1);
    reinterpret_cast<uint2*>(lo)[j] = make_uint2(l0, l1);
}

// ============================================================
// Tensor-core SGEMM, fp16. Template ALO:
//  ALO=0: 2-term  C = Ah*Bh + Ah*Bl     (A single)
//  ALO=1: 3-term  C = Ah*Bh + Ah*Bl + Al*Bh
// cp.async 2-stage, 512 threads (16 warps 4x4), 128x128 tile,
// K-chunk 32, 80B rows (conflict-free).
// ============================================================
#define GROWB 80
#define GARR  (128 * GROWB)   // 10240

template<int ALO>
__global__ __launch_bounds__(512, 1) void sgemm_tc(
    const __half* __restrict__ Ahi, const __half* __restrict__ Alo,
    const __half* __restrict__ Bhi, const __half* __restrict__ Blo,
    const float* __restrict__ bias, const float* __restrict__ residual,
    float* __restrict__ C,
    __half* __restrict__ Shi, __half* __restrict__ Slo,
    int qsplit, int K, int N)
{
    extern __shared__ unsigned char smem[];
    const u32 sb = smem_u32(smem);
    constexpr u32 OFF_BHI = (u32)(1 + ALO) * GARR;
    constexpr u32 OFF_BLO = (u32)(2 + ALO) * GARR;
    constexpr u32 BUFSZ   = (u32)(3 + ALO) * GARR;

    const int tid = threadIdx.x;
    const int wid = tid >> 5, lid = tid & 31;
    const int rowBase = blockIdx.y * 128;
    const int colBase = blockIdx.x * 128;
    const int warp_m = (wid >> 2) * 32;
    const int warp_n = (wid & 3) * 32;

    const int lrow = tid >> 2;
    const int lc4  = tid & 3;
    const u32 so   = (u32)lrow * GROWB + (u32)lc4 * 16;
    const char* pAhi = (const char*)Ahi + ((size_t)(rowBase + lrow) * K) * 2 + lc4 * 16;
    const char* pAlo = ALO ? (const char*)Alo + ((size_t)(rowBase + lrow) * K) * 2 + lc4 * 16 : nullptr;
    const char* pBhi = (const char*)Bhi + ((size_t)(colBase + lrow) * K) * 2 + lc4 * 16;
    const char* pBlo = (const char*)Blo + ((size_t)(colBase + lrow) * K) * 2 + lc4 * 16;

    const int a_row = warp_m + (lid & 15);
    const u32 a_kb  = (u32)(lid >> 4) * 16;
    const int b_n   = warp_n + (lid & 7) + ((lid >> 4) << 3);
    const u32 b_kb  = (u32)((lid >> 3) & 1) * 16;

    float acc[2][4][4];
    #pragma unroll
    for (int i = 0; i < 2; i++)
        #pragma unroll
        for (int j = 0; j < 4; j++)
            #pragma unroll
            for (int q = 0; q < 4; q++) acc[i][j][q] = 0.f;

    const int nChunk = K >> 5;
    {
        u32 d = sb + so;
        cpa16(d, pAhi);
        if (ALO) cpa16(d + GARR, pAlo);
        cpa16(d + OFF_BHI, pBhi);
        cpa16(d + OFF_BLO, pBlo);
        CP_COMMIT();
    }

    for (int c = 0; c < nChunk; c++) {
        CP_WAIT0();
        __syncthreads();
        if (c + 1 < nChunk) {
            u32 d = sb + (u32)((c + 1) & 1) * BUFSZ + so;
            size_t kb = (size_t)(c + 1) * 64;
            cpa16(d, pAhi + kb);
            if (ALO) cpa16(d + GARR, pAlo + kb);
            cpa16(d + OFF_BHI, pBhi + kb);
            cpa16(d + OFF_BLO, pBlo + kb);
            CP_COMMIT();
        }

        const u32 bufo = (u32)(c & 1) * BUFSZ;
        #pragma unroll
        for (int ks = 0; ks < 2; ks++) {
            const u32 kso = (u32)ks * 32;
            u32 bhi[2][4], blo[2][4];
            #pragma unroll
            for (int np = 0; np < 2; np++) {
                u32 ba = sb + bufo + (u32)(b_n + np * 16) * GROWB + kso + b_kb;
                ldsm4(bhi[np], ba + OFF_BHI);
                ldsm4(blo[np], ba + OFF_BLO);
            }
            #pragma unroll
            for (int mt = 0; mt < 2; mt++) {
                u32 aa = sb + bufo + (u32)(a_row + mt * 16) * GROWB + kso + a_kb;
                u32 ahi[4], alo[4];
                ldsm4(ahi, aa);
                if (ALO) ldsm4(alo, aa + GARR);
                #pragma unroll
                for (int nt = 0; nt < 4; nt++) {
                    const u32* bh = &bhi[nt >> 1][(nt & 1) * 2];
                    const u32* bl = &blo[nt >> 1][(nt & 1) * 2];
                    mma16816(acc[mt][nt], ahi, bh);
                    mma16816(acc[mt][nt], ahi, bl);
                    if (ALO) mma16816(acc[mt][nt], alo, bh);
                }
            }
        }
    }

    const int frow = lid >> 2;
    const int fcol = (lid & 3) * 2;
    #pragma unroll
    for (int mt = 0; mt < 2; mt++) {
        #pragma unroll
        for (int nt = 0; nt < 4; nt++) {
            int col = colBase + warp_n + nt * 8 + fcol;
            float2 bi = *reinterpret_cast<const float2*>(bias + col);
            #pragma unroll
            for (int half = 0; half < 2; half++) {
                int r = rowBase + warp_m + mt * 16 + frow + half * 8;
                float2 o;
                o.x = acc[mt][nt][half * 2 + 0] + bi.x;
                o.y = acc[mt][nt][half * 2 + 1] + bi.y;
                if (residual) {
                    float2 rv = *reinterpret_cast<const float2*>(residual + (size_t)r * N + col);
                    o.x += rv.x; o.y += rv.y;
                }
                if (C)
                    *reinterpret_cast<float2*>(C + (size_t)r * N + col) = o;
                if (Shi) {
                    float sc = (qsplit && col < 512) ? 0.125f : 1.0f;
                    u32 hb, lb;
                    h2_split(o.x * sc, o.y * sc, hb, lb);
                    *reinterpret_cast<u32*>(Shi + (size_t)r * N + col) = hb;
                    if (Slo)
                        *reinterpret_cast<u32*>(Slo + (size_t)r * N + col) = lb;
                }
            }
        }
    }
}

// ============================================================
// Tensor-core flash attention, fp16 2-term:
// S = Qh*(Kh+Kl), O += Ph*(Vh+Vl). q-tile 96, 6 warps,
// cp.async double-buffered K/V. Output single fp16.
// ============================================================
#define ROWB 144
#define QT 96
#define KV_KHI 0
#define KV_KLO 9216
#define KV_VHI 18432
#define KV_VLO 27648
#define KVBUF  36864
#define AQ_HI  KVBUF
#define ATTN_SMEM (2 * KVBUF)

__global__ __launch_bounds__(192) void attn_tc(
    const __half* __restrict__ ghi, const __half* __restrict__ glo,
    __half* __restrict__ ohi)
{
    extern __shared__ unsigned char smem[];
    const u32 sb = smem_u32(smem);

    const int tid = threadIdx.x;
    const int wid = tid >> 5, lid = tid & 31;
    const int bh = blockIdx.y;
    const int b = bh >> 3, h = bh & 7;
    const int q0 = blockIdx.x * QT;

    const __half* qhi = ghi + (size_t)(b * Nn + q0) * 1536 + h * 64;
    const __half* khi = ghi + (size_t)(b * Nn) * 1536 + 512  + h * 64;
    const __half* klo = glo + (size_t)(b * Nn) * 1536 + 512  + h * 64;
    const __half* vhi = ghi + (size_t)(b * Nn) * 1536 + 1024 + h * 64;
    const __half* vlo = glo + (size_t)(b * Nn) * 1536 + 1024 + h * 64;

    // prefetch K/V chunk 0 + stage Q (hi only)
    for (int s = tid; s < 512; s += 192) {
        int row = s >> 3, c8 = s & 7;
        size_t go = (size_t)row * 1536 + c8 * 8;
        u32 so = sb + (u32)row * ROWB + (u32)c8 * 16;
        cpa16(so + KV_KHI, khi + go);
        cpa16(so + KV_KLO, klo + go);
        cpa16(so + KV_VHI, vhi + go);
        cpa16(so + KV_VLO, vlo + go);
    }
    #pragma unroll
    for (int it = 0; it < 4; it++) {
        int s = tid + it * 192;   // 0..767
        int row = s >> 3, c8 = s & 7;
        size_t go = (size_t)row * 1536 + c8 * 8;
        u32 so = sb + (u32)row * ROWB + (u32)c8 * 16;
        cpa16(so + AQ_HI, qhi + go);
    }
    CP_COMMIT();
    CP_WAIT0();
    __syncthreads();

    // hoist Q fragments (hi only)
    u32 qh[4][4];
    {
        const int a_row = (wid << 4) + (lid & 15);
        const u32 a_kb = (u32)(lid >> 4) * 16;
        #pragma unroll
        for (int kt = 0; kt < 4; kt++) {
            u32 addr = sb + AQ_HI + (u32)a_row * ROWB + (u32)kt * 32 + a_kb;
            ldsm4(qh[kt], addr);
        }
    }
    __syncthreads();

    float m_lo = -1e30f, m_hi = -1e30f, l_lo = 0.f, l_hi = 0.f;
    float oacc[8][4];
    #pragma unroll
    for (int j = 0; j < 8; j++)
        #pragma unroll
        for (int q = 0; q < 4; q++) oacc[j][q] = 0.f;

    const int kb_row = (lid & 7) + ((lid >> 4) << 3);
    const u32 kb_kb  = (u32)((lid >> 3) & 1) * 16;
    const int vb_key = (lid & 7) + (((lid >> 3) & 1) << 3);
    const u32 vb_db  = (u32)(lid >> 4) * 16;

    const int nChunk = Nn / 64;
    for (int c = 0; c < nChunk; c++) {
        if (c + 1 < nChunk) {
            const u32 nb = sb + (u32)((c + 1) & 1) * KVBUF;
            const int kc1 = (c + 1) * 64;
            for (int s = tid; s < 512; s += 192) {
                int row = s >> 3, c8 = s & 7;
                size_t go = (size_t)(kc1 + row) * 1536 + c8 * 8;
                u32 so = nb + (u32)row * ROWB + (u32)c8 * 16;
                cpa16(so + KV_KHI, khi + go);
                cpa16(so + KV_KLO, klo + go);
                cpa16(so + KV_VHI, vhi + go);
                cpa16(so + KV_VLO, vlo + go);
            }
        }
        CP_COMMIT();

        const u32 bufb = sb + (u32)(c & 1) * KVBUF;

        // ---- S = Qh (Kh + Kl) ----
        float sacc[8][4];
        #pragma unroll
        for (int j = 0; j < 8; j++)
            #pragma unroll
            for (int q = 0; q < 4; q++) sacc[j][q] = 0.f;

        #pragma unroll
        for (int kt = 0; kt < 4; kt++) {
            #pragma unroll
            for (int ng = 0; ng < 4; ng++) {
                u32 ka = bufb + KV_KHI + (u32)(ng * 16 + kb_row) * ROWB + (u32)kt * 32 + kb_kb;
                u32 kh[4], kl[4];
                ldsm4(kh, ka);
                ldsm4(kl, ka + (KV_KLO - KV_KHI));
                #pragma unroll
                for (int half = 0; half < 2; half++) {
                    float* s = sacc[2 * ng + half];
                    mma16816(s, qh[kt], &kh[half * 2]);
                    mma16816(s, qh[kt], &kl[half * 2]);
                }
            }
        }

        // ---- fragment online softmax ----
        float mx_lo = -1e30f, mx_hi = -1e30f;
        #pragma unroll
        for (int j = 0; j < 8; j++) {
            mx_lo = fmaxf(mx_lo, fmaxf(sacc[j][0], sacc[j][1]));
            mx_hi = fmaxf(mx_hi, fmaxf(sacc[j][2], sacc[j][3]));
        }
        #pragma unroll
        for (int o = 1; o <= 2; o <<= 1) {
            mx_lo = fmaxf(mx_lo, __shfl_xor_sync(0xffffffffu, mx_lo, o));
            mx_hi = fmaxf(mx_hi, __shfl_xor_sync(0xffffffffu, mx_hi, o));
        }
        float mn_lo = fmaxf(m_lo, mx_lo), mn_hi = fmaxf(m_hi, mx_hi);
        float corr_lo = __expf(m_lo - mn_lo), corr_hi = __expf(m_hi - mn_hi);
        float rs_lo = 0.f, rs_hi = 0.f;
        #pragma unroll
        for (int j = 0; j < 8; j++) {
            sacc[j][0] = __expf(sacc[j][0] - mn_lo);
            sacc[j][1] = __expf(sacc[j][1] - mn_lo);
            sacc[j][2] = __expf(sacc[j][2] - mn_hi);
            sacc[j][3] = __expf(sacc[j][3] - mn_hi);
            rs_lo += sacc[j][0] + sacc[j][1];
            rs_hi += sacc[j][2] + sacc[j][3];
        }
        #pragma unroll
        for (int o = 1; o <= 2; o <<= 1) {
            rs_lo += __shfl_xor_sync(0xffffffffu, rs_lo, o);
            rs_hi += __shfl_xor_sync(0xffffffffu, rs_hi, o);
        }
        l_lo = l_lo * corr_lo + rs_lo;
        l_hi = l_hi * corr_hi + rs_hi;
        m_lo = mn_lo; m_hi = mn_hi;
        #pragma unroll
        for (int j = 0; j < 8; j++) {
            oacc[j][0] *= corr_lo; oacc[j][1] *= corr_lo;
            oacc[j][2] *= corr_hi; oacc[j][3] *= corr_hi;
        }

        // ---- O += Ph (Vh + Vl) ----
        #pragma unroll
        for (int kt = 0; kt < 4; kt++) {
            const int j0 = 2 * kt, j1 = 2 * kt + 1;
            u32 aph[4];
            aph[0] = h2pack(sacc[j0][0], sacc[j0][1]);
            aph[1] = h2pack(sacc[j0][2], sacc[j0][3]);
            aph[2] = h2pack(sacc[j1][0], sacc[j1][1]);
            aph[3] = h2pack(sacc[j1][2], sacc[j1][3]);
            #pragma unroll
            for (int ng = 0; ng < 4; ng++) {
                u32 va = bufb + KV_VHI + (u32)(kt * 16 + vb_key) * ROWB + (u32)ng * 32 + vb_db;
                u32 vh[4], vl[4];
                ldsm4t(vh, va);
                ldsm4t(vl, va + (KV_VLO - KV_VHI));
                #pragma unroll
                for (int half = 0; half < 2; half++) {
                    float* oa = oacc[2 * ng + half];
                    mma16816(oa, aph, &vh[half * 2]);
                    mma16816(oa, aph, &vl[half * 2]);
                }
            }
        }

        CP_WAIT0();
        __syncthreads();
    }

    // ---- write O (single fp16) ----
    const float inv_lo = 1.f / l_lo, inv_hi = 1.f / l_hi;
    const int r_lo = q0 + (wid << 4) + (lid >> 2);
    const int cb = h * 64 + (lid & 3) * 2;
    #pragma unroll
    for (int j = 0; j < 8; j++) {
        int col = cb + j * 8;
        u32 w0 = h2pack(oacc[j][0] * inv_lo, oacc[j][1] * inv_lo);
        u32 w1r = h2pack(oacc[j][2] * inv_hi, oacc[j][3] * inv_hi);
        *reinterpret_cast<u32*>(ohi + (size_t)(b * Nn + r_lo) * Dd + col)     = w0;
        *reinterpret_cast<u32*>(ohi + (size_t)(b * Nn + r_lo + 8) * Dd + col) = w1r;
    }
}

// ============================================================
// FUSED: LayerNorm -> GELU -> comp -> outer -> top-51 -> write
// (R10-passing, unchanged)
// ============================================================
__global__ __launch_bounds__(512) void ln_outer_topk_kernel(
    const float* __restrict__ hsrc,
    const float* __restrict__ ln_g, const float* __restrict__ ln_b,
    const float* __restrict__ w2,  const float* __restrict__ b2,
    const float* __restrict__ F, const float* __restrict__ templates,
    float* __restrict__ out)
{
    __shared__ float s[512];
    __shared__ float Frow[512];
    __shared__ float red[32];
    __shared__ float cs[16];
    __shared__ float Qout[512 * 17];

    const int row = blockIdx.x;
    const int tid = threadIdx.x;
    const int m = tid >> 5, lid = tid & 31;

    float x = hsrc[(size_t)row * 512 + tid];
    s[tid] = x;
    Frow[tid] = F[(size_t)row * 512 + tid];

    float sum = x, sq = x * x;
    #pragma unroll
    for (int o = 16; o >= 1; o >>= 1) {
        sum += __shfl_xor_sync(0xffffffffu, sum, o);
        sq  += __shfl_xor_sync(0xffffffffu, sq,  o);
    }
    if (lid == 0) { red[m] = sum; red[m + 16] = sq; }
    __syncthreads();
    if (tid == 0) {
        float S = 0.f, Q = 0.f;
        #pragma unroll
        for (int i = 0; i < 16; i++) { S += red[i]; Q += red[i + 16]; }
        red[0] = S * (1.f / 512.f);
        red[16] = Q * (1.f / 512.f);
    }
    __syncthreads();
    const float mean = red[0];
    const float rstd = rsqrtf(red[16] - mean * mean + 1e-5f);

    float g = (x - mean) * rstd * ln_g[tid] + ln_b[tid];
    g = 0.5f * g * (1.f + erff(g * 0.70710678118f));
    __syncthreads();
    s[tid] = g;
    __syncthreads();

    {
        float p = 0.f;
        const float* wrow = w2 + m * 512;
        #pragma unroll
        for (int i = 0; i < 16; i++) {
            int e = lid + 32 * i;
            p += s[e] * wrow[e];
        }
        #pragma unroll
        for (int o = 16; o >= 1; o >>= 1)
            p += __shfl_xor_sync(0xffffffffu, p, o);
        if (lid == 0) cs[m] = p + b2[m];
    }
    __syncthreads();

    const float c = cs[m];
    float    qv[16];
    unsigned key[16];
    unsigned mx = 0;
    #pragma unroll
    for (int i = 0; i < 16; i++) {
        int d = lid + 32 * i;
        float q = Frow[d] * templates[m * 512 + d] * c;
        qv[i]  = q;
        key[i] = __float_as_uint(fabsf(q));
        mx = max(mx, key[i]);
    }
    #pragma unroll
    for (int o = 16; o >= 1; o >>= 1)
        mx = max(mx, __shfl_xor_sync(0xffffffffu, mx, o));

    unsigned prefix = 0;
    int bit = 31 - __clz(mx | 1u);
    for (; bit >= 0; bit--) {
        unsigned test = prefix | (1u << bit);
        int cnt = 0;
        #pragma unroll
        for (int i = 0; i < 16; i++) cnt += (key[i] >= test);
        cnt = __reduce_add_sync(0xffffffffu, cnt);
        if (cnt >= KTOP) {
            prefix = test;
            if (cnt == KTOP) break;
        }
    }

    #pragma unroll
    for (int i = 0; i < 16; i++) {
        int d = lid + 32 * i;
        Qout[d * 17 + m] = (key[i] >= prefix) ? qv[i] : 0.f;
    }
    __syncthreads();

    float* ob = out + (size_t)row * (512 * 16);
    #pragma unroll
    for (int i = 0; i < 16; i++) {
        int e = tid + 512 * i;
        ob[e] = Qout[(e >> 4) * 17 + (e & 15)];
    }
}

// ============================================================
extern "C" void kernel_launch(void* const* d_in, const int* in_sizes, int n_in,
                              void* d_out, int out_size) {
    const float* F    = (const float*)d_in[0];
    const float* Wqkv = (const float*)d_in[1];
    const float* bqkv = (const float*)d_in[2];
    const float* Wout = (const float*)d_in[3];
    const float* bout = (const float*)d_in[4];
    const float* w1   = (const float*)d_in[5];
    const float* b1   = (const float*)d_in[6];
    const float* lng  = (const float*)d_in[7];
    const float* lnb  = (const float*)d_in[8];
    const float* w2   = (const float*)d_in[9];
    const float* b2   = (const float*)d_in[10];
    const float* tmpl = (const float*)d_in[11];
    float* out = (float*)d_out;

    __half *qhi, *qlo, *Fhi, *wqh, *wql, *woh, *wol, *w1h, *w1l;
    __half *athi, *fehi, *felo;
    float *hbuf;
    cudaGetSymbolAddress((void**)&qhi,  g_qhi);
    cudaGetSymbolAddress((void**)&qlo,  g_qlo);
    cudaGetSymbolAddress((void**)&Fhi,  g_Fhi);
    cudaGetSymbolAddress((void**)&wqh,  g_wqh);
    cudaGetSymbolAddress((void**)&wql,  g_wql);
    cudaGetSymbolAddress((void**)&woh,  g_woh);
    cudaGetSymbolAddress((void**)&wol,  g_wol);
    cudaGetSymbolAddress((void**)&w1h,  g_w1h);
    cudaGetSymbolAddress((void**)&w1l,  g_w1l);
    cudaGetSymbolAddress((void**)&athi, g_athi);
    cudaGetSymbolAddress((void**)&fehi, g_fehi);
    cudaGetSymbolAddress((void**)&felo, g_felo);
    cudaGetSymbolAddress((void**)&hbuf, g_h);

    const int SM2 = 2 * 3 * GARR;   // 61440 (2-term)
    const int SM3 = 2 * 4 * GARR;   // 81920 (3-term)
    cudaFuncSetAttribute(sgemm_tc<0>, cudaFuncAttributeMaxDynamicSharedMemorySize, SM2);
    cudaFuncSetAttribute(sgemm_tc<1>, cudaFuncAttributeMaxDynamicSharedMemorySize, SM3);
    cudaFuncSetAttribute(attn_tc, cudaFuncAttributeMaxDynamicSharedMemorySize, ATTN_SMEM);

    // split F (hi) + weights (hi/lo)
    split_all_kernel<<<(SEG3 + 255) / 256, 256>>>(
        F, Wqkv, Wout, w1, Fhi, wqh, wql, woh, wol, w1h, w1l);

    // qkv = F @ Wqkv^T + bqkv (2-term) -> split fp16 (Q scaled 1/8)
    sgemm_tc<0><<<dim3(1536 / 128, BN / 128), 512, SM2>>>(
        Fhi, nullptr, wqh, wql, bqkv, nullptr, nullptr, qhi, qlo, 1, 512, 1536);
    // attention (2-term) -> single fp16 O
    attn_tc<<<dim3(Nn / QT, Bb * Hh), 192, ATTN_SMEM>>>(qhi, qlo, athi);
    // fenh = F + O @ Wout^T + bout (2-term) -> split fp16
    sgemm_tc<0><<<dim3(512 / 128, BN / 128), 512, SM2>>>(
        athi, nullptr, woh, wol, bout, F, nullptr, fehi, felo, 0, 512, 512);
    // h = fenh @ w1^T + b1 (3-term, direct output path) -> fp32
    sgemm_tc<1><<<dim3(512 / 128, BN / 128), 512, SM3>>>(
        fehi, felo, w1h, w1l, b1, nullptr, hbuf, nullptr, nullptr, 0, 512, 512);
    // fused LN -> GELU -> comp -> outer -> topk -> write
    ln_outer_topk_kernel<<<BN, 512>>>(hbuf, lng, lnb, w2, b2, F, tmpl, out);
}

// round 13
// speedup vs baseline: 1.4402x; 1.2329x over previous
#include <cuda_runtime.h>
#include <cuda_fp16.h>
#include <math.h>

#define Bb   8
#define Nn   576
#define Dd   512
#define Mm   16
#define Hh   8
#define BN   (Bb*Nn)      // 4608
#define KTOP 51

typedef unsigned long long u64;
typedef unsigned int u32;

__device__ __forceinline__ u32 smem_u32(const void* p) {
    u32 a; asm("{ .reg .u64 t; cvta.to.shared.u64 t, %1; cvt.u32.u64 %0, t; }"
               : "=r"(a) : "l"(p));
    return a;
}

// ---- mma.sync helpers (fp16 in, fp32 acc) ----
__device__ __forceinline__ void ldsm4(u32* r, u32 addr) {
    asm volatile("ldmatrix.sync.aligned.m8n8.x4.shared.b16 {%0,%1,%2,%3}, [%4];"
                 : "=r"(r[0]), "=r"(r[1]), "=r"(r[2]), "=r"(r[3]) : "r"(addr));
}
__device__ __forceinline__ void ldsm4t(u32* r, u32 addr) {
    asm volatile("ldmatrix.sync.aligned.m8n8.x4.trans.shared.b16 {%0,%1,%2,%3}, [%4];"
                 : "=r"(r[0]), "=r"(r[1]), "=r"(r[2]), "=r"(r[3]) : "r"(addr));
}
__device__ __forceinline__ void mma16816(float* c, const u32* a, const u32* b) {
    asm volatile(
        "mma.sync.aligned.m16n8k16.row.col.f32.f16.f16.f32 "
        "{%0,%1,%2,%3}, {%4,%5,%6,%7}, {%8,%9}, {%0,%1,%2,%3};"
        : "+f"(c[0]), "+f"(c[1]), "+f"(c[2]), "+f"(c[3])
        : "r"(a[0]), "r"(a[1]), "r"(a[2]), "r"(a[3]), "r"(b[0]), "r"(b[1]));
}
__device__ __forceinline__ u32 h2pack(float x, float y) {
    __half2 h = __floats2half2_rn(x, y);
    return *(u32*)&h;
}

// ---- cp.async ----
__device__ __forceinline__ void cpa16(u32 saddr, const void* g) {
    asm volatile("cp.async.cg.shared.global [%0], [%1], 16;" :: "r"(saddr), "l"(g));
}
#define CP_COMMIT() asm volatile("cp.async.commit_group;" ::: "memory")
#define CP_WAIT0()  asm volatile("cp.async.wait_group 0;" ::: "memory")

// ---- scratch (fp16, single precision term) ----
__device__ __half g_qkv[BN * 3 * Dd];   // qkv (Q pre-scaled 1/8)
__device__ __half g_F16[BN * Dd];
__device__ __half g_wq [3*Dd*Dd];
__device__ __half g_wo [Dd*Dd];
__device__ __half g_w1 [Dd*Dd];
__device__ __half g_at [BN * Dd];       // attention out
__device__ __half g_fe [BN * Dd];       // fenh
__device__ float  g_h  [BN * Dd];

// ============================================================
// One-launch fp32 -> fp16 convert over 4 tensors
// ============================================================
#define SEG0 589824
#define SEG1 (SEG0 + 196608)
#define SEG2 (SEG1 + 65536)
#define SEG3 (SEG2 + 65536)

__global__ __launch_bounds__(256) void cvt_all_kernel(
    const float* __restrict__ F,    const float* __restrict__ Wqkv,
    const float* __restrict__ Wout, const float* __restrict__ w1,
    __half* __restrict__ F16, __half* __restrict__ wq,
    __half* __restrict__ wo,  __half* __restrict__ w1h)
{
    int i = blockIdx.x * 256 + threadIdx.x;
    if (i >= SEG3) return;
    const float* src; __half* dst; int j;
    if (i < SEG0)      { src = F;    dst = F16; j = i; }
    else if (i < SEG1) { src = Wqkv; dst = wq;  j = i - SEG0; }
    else if (i < SEG2) { src = Wout; dst = wo;  j = i - SEG1; }
    else               { src = w1;   dst = w1h; j = i - SEG2; }
    float4 v = reinterpret_cast<const float4*>(src)[j];
    u32 h0 = h2pack(v.x, v.y), h1 = h2pack(v.z, v.w);
    reinterpret_cast<uint2*>(dst)[j] = make_uint2(h0, h1);
}

// ============================================================
// Tensor-core HGEMM: C = A*B^T + bias (+res). Plain fp16 1-term.
// cp.async 2-stage, 512 threads (16 warps 4x4), 128x128 tile,
// K-chunk 32, 80B rows (conflict-free).
// ============================================================
#define GROWB 80
#define GARR  (128 * GROWB)   // 10240
#define GBUFSZ (2 * GARR)     // A + B
#define GEMM_SMEM (2 * GBUFSZ) // 40960

__global__ __launch_bounds__(512, 1) void sgemm_tc(
    const __half* __restrict__ A, const __half* __restrict__ B,
    const float* __restrict__ bias, const float* __restrict__ residual,
    float* __restrict__ C, __half* __restrict__ S16,
    int qsplit, int K, int N)
{
    extern __shared__ unsigned char smem[];
    const u32 sb = smem_u32(smem);

    const int tid = threadIdx.x;
    const int wid = tid >> 5, lid = tid & 31;
    const int rowBase = blockIdx.y * 128;
    const int colBase = blockIdx.x * 128;
    const int warp_m = (wid >> 2) * 32;
    const int warp_n = (wid & 3) * 32;

    const int lrow = tid >> 2;
    const int lc4  = tid & 3;
    const u32 so   = (u32)lrow * GROWB + (u32)lc4 * 16;
    const char* pA = (const char*)A + ((size_t)(rowBase + lrow) * K) * 2 + lc4 * 16;
    const char* pB = (const char*)B + ((size_t)(colBase + lrow) * K) * 2 + lc4 * 16;

    const int a_row = warp_m + (lid & 15);
    const u32 a_kb  = (u32)(lid >> 4) * 16;
    const int b_n   = warp_n + (lid & 7) + ((lid >> 4) << 3);
    const u32 b_kb  = (u32)((lid >> 3) & 1) * 16;

    float acc[2][4][4];
    #pragma unroll
    for (int i = 0; i < 2; i++)
        #pragma unroll
        for (int j = 0; j < 4; j++)
            #pragma unroll
            for (int q = 0; q < 4; q++) acc[i][j][q] = 0.f;

    const int nChunk = K >> 5;
    {
        u32 d = sb + so;
        cpa16(d, pA);
        cpa16(d + GARR, pB);
        CP_COMMIT();
    }

    for (int c = 0; c < nChunk; c++) {
        CP_WAIT0();
        __syncthreads();
        if (c + 1 < nChunk) {
            u32 d = sb + (u32)((c + 1) & 1) * GBUFSZ + so;
            size_t kb = (size_t)(c + 1) * 64;
            cpa16(d, pA + kb);
            cpa16(d + GARR, pB + kb);
            CP_COMMIT();
        }

        const u32 bufo = (u32)(c & 1) * GBUFSZ;
        #pragma unroll
        for (int ks = 0; ks < 2; ks++) {
            const u32 kso = (u32)ks * 32;
            u32 bfr[2][4];
            #pragma unroll
            for (int np = 0; np < 2; np++) {
                u32 ba = sb + bufo + GARR + (u32)(b_n + np * 16) * GROWB + kso + b_kb;
                ldsm4(bfr[np], ba);
            }
            #pragma unroll
            for (int mt = 0; mt < 2; mt++) {
                u32 aa = sb + bufo + (u32)(a_row + mt * 16) * GROWB + kso + a_kb;
                u32 afr[4];
                ldsm4(afr, aa);
                #pragma unroll
                for (int nt = 0; nt < 4; nt++)
                    mma16816(acc[mt][nt], afr, &bfr[nt >> 1][(nt & 1) * 2]);
            }
        }
    }

    const int frow = lid >> 2;
    const int fcol = (lid & 3) * 2;
    #pragma unroll
    for (int mt = 0; mt < 2; mt++) {
        #pragma unroll
        for (int nt = 0; nt < 4; nt++) {
            int col = colBase + warp_n + nt * 8 + fcol;
            float2 bi = *reinterpret_cast<const float2*>(bias + col);
            #pragma unroll
            for (int half = 0; half < 2; half++) {
                int r = rowBase + warp_m + mt * 16 + frow + half * 8;
                float2 o;
                o.x = acc[mt][nt][half * 2 + 0] + bi.x;
                o.y = acc[mt][nt][half * 2 + 1] + bi.y;
                if (residual) {
                    float2 rv = *reinterpret_cast<const float2*>(residual + (size_t)r * N + col);
                    o.x += rv.x; o.y += rv.y;
                }
                if (C)
                    *reinterpret_cast<float2*>(C + (size_t)r * N + col) = o;
                if (S16) {
                    float sc = (qsplit && col < 512) ? 0.125f : 1.0f;
                    *reinterpret_cast<u32*>(S16 + (size_t)r * N + col) =
                        h2pack(o.x * sc, o.y * sc);
                }
            }
        }
    }
}

// ============================================================
// Tensor-core flash attention, plain fp16.
// q-tile 96, 6 warps, cp.async double-buffered K/V.
// ============================================================
#define ROWB 144
#define QT 96
#define KV_K 0
#define KV_V 9216
#define KVBUF 18432
#define AQ   (2 * KVBUF)           // Q staging region
#define ATTN_SMEM (2 * KVBUF + 13824)   // 50688

__global__ __launch_bounds__(192) void attn_tc(
    const __half* __restrict__ qkv, __half* __restrict__ oat)
{
    extern __shared__ unsigned char smem[];
    const u32 sb = smem_u32(smem);

    const int tid = threadIdx.x;
    const int wid = tid >> 5, lid = tid & 31;
    const int bh = blockIdx.y;
    const int b = bh >> 3, h = bh & 7;
    const int q0 = blockIdx.x * QT;

    const __half* qp = qkv + (size_t)(b * Nn + q0) * 1536 + h * 64;
    const __half* kp = qkv + (size_t)(b * Nn) * 1536 + 512  + h * 64;
    const __half* vp = qkv + (size_t)(b * Nn) * 1536 + 1024 + h * 64;

    // prefetch K/V chunk 0 + stage Q
    for (int s = tid; s < 512; s += 192) {
        int row = s >> 3, c8 = s & 7;
        size_t go = (size_t)row * 1536 + c8 * 8;
        u32 so = sb + (u32)row * ROWB + (u32)c8 * 16;
        cpa16(so + KV_K, kp + go);
        cpa16(so + KV_V, vp + go);
    }
    #pragma unroll
    for (int it = 0; it < 4; it++) {
        int s = tid + it * 192;   // 0..767
        int row = s >> 3, c8 = s & 7;
        size_t go = (size_t)row * 1536 + c8 * 8;
        cpa16(sb + AQ + (u32)row * ROWB + (u32)c8 * 16, qp + go);
    }
    CP_COMMIT();
    CP_WAIT0();
    __syncthreads();

    // hoist Q fragments
    u32 qf[4][4];
    {
        const int a_row = (wid << 4) + (lid & 15);
        const u32 a_kb = (u32)(lid >> 4) * 16;
        #pragma unroll
        for (int kt = 0; kt < 4; kt++)
            ldsm4(qf[kt], sb + AQ + (u32)a_row * ROWB + (u32)kt * 32 + a_kb);
    }

    float m_lo = -1e30f, m_hi = -1e30f, l_lo = 0.f, l_hi = 0.f;
    float oacc[8][4];
    #pragma unroll
    for (int j = 0; j < 8; j++)
        #pragma unroll
        for (int q = 0; q < 4; q++) oacc[j][q] = 0.f;

    const int kb_row = (lid & 7) + ((lid >> 4) << 3);
    const u32 kb_kb  = (u32)((lid >> 3) & 1) * 16;
    const int vb_key = (lid & 7) + (((lid >> 3) & 1) << 3);
    const u32 vb_db  = (u32)(lid >> 4) * 16;

    const int nChunk = Nn / 64;
    for (int c = 0; c < nChunk; c++) {
        if (c + 1 < nChunk) {
            const u32 nb = sb + (u32)((c + 1) & 1) * KVBUF;
            const int kc1 = (c + 1) * 64;
            for (int s = tid; s < 512; s += 192) {
                int row = s >> 3, c8 = s & 7;
                size_t go = (size_t)(kc1 + row) * 1536 + c8 * 8;
                u32 so = nb + (u32)row * ROWB + (u32)c8 * 16;
                cpa16(so + KV_K, kp + go);
                cpa16(so + KV_V, vp + go);
            }
        }
        CP_COMMIT();

        const u32 bufb = sb + (u32)(c & 1) * KVBUF;

        // ---- S = Q K^T ----
        float sacc[8][4];
        #pragma unroll
        for (int j = 0; j < 8; j++)
            #pragma unroll
            for (int q = 0; q < 4; q++) sacc[j][q] = 0.f;

        #pragma unroll
        for (int kt = 0; kt < 4; kt++) {
            #pragma unroll
            for (int ng = 0; ng < 4; ng++) {
                u32 ka = bufb + KV_K + (u32)(ng * 16 + kb_row) * ROWB + (u32)kt * 32 + kb_kb;
                u32 kf[4];
                ldsm4(kf, ka);
                mma16816(sacc[2 * ng + 0], qf[kt], &kf[0]);
                mma16816(sacc[2 * ng + 1], qf[kt], &kf[2]);
            }
        }

        // ---- fragment online softmax ----
        float mx_lo = -1e30f, mx_hi = -1e30f;
        #pragma unroll
        for (int j = 0; j < 8; j++) {
            mx_lo = fmaxf(mx_lo, fmaxf(sacc[j][0], sacc[j][1]));
            mx_hi = fmaxf(mx_hi, fmaxf(sacc[j][2], sacc[j][3]));
        }
        #pragma unroll
        for (int o = 1; o <= 2; o <<= 1) {
            mx_lo = fmaxf(mx_lo, __shfl_xor_sync(0xffffffffu, mx_lo, o));
            mx_hi = fmaxf(mx_hi, __shfl_xor_sync(0xffffffffu, mx_hi, o));
        }
        float mn_lo = fmaxf(m_lo, mx_lo), mn_hi = fmaxf(m_hi, mx_hi);
        float corr_lo = __expf(m_lo - mn_lo), corr_hi = __expf(m_hi - mn_hi);
        float rs_lo = 0.f, rs_hi = 0.f;
        #pragma unroll
        for (int j = 0; j < 8; j++) {
            sacc[j][0] = __expf(sacc[j][0] - mn_lo);
            sacc[j][1] = __expf(sacc[j][1] - mn_lo);
            sacc[j][2] = __expf(sacc[j][2] - mn_hi);
            sacc[j][3] = __expf(sacc[j][3] - mn_hi);
            rs_lo += sacc[j][0] + sacc[j][1];
            rs_hi += sacc[j][2] + sacc[j][3];
        }
        #pragma unroll
        for (int o = 1; o <= 2; o <<= 1) {
            rs_lo += __shfl_xor_sync(0xffffffffu, rs_lo, o);
            rs_hi += __shfl_xor_sync(0xffffffffu, rs_hi, o);
        }
        l_lo = l_lo * corr_lo + rs_lo;
        l_hi = l_hi * corr_hi + rs_hi;
        m_lo = mn_lo; m_hi = mn_hi;
        #pragma unroll
        for (int j = 0; j < 8; j++) {
            oacc[j][0] *= corr_lo; oacc[j][1] *= corr_lo;
            oacc[j][2] *= corr_hi; oacc[j][3] *= corr_hi;
        }

        // ---- O += P V ----
        #pragma unroll
        for (int kt = 0; kt < 4; kt++) {
            const int j0 = 2 * kt, j1 = 2 * kt + 1;
            u32 ap[4];
            ap[0] = h2pack(sacc[j0][0], sacc[j0][1]);
            ap[1] = h2pack(sacc[j0][2], sacc[j0][3]);
            ap[2] = h2pack(sacc[j1][0], sacc[j1][1]);
            ap[3] = h2pack(sacc[j1][2], sacc[j1][3]);
            #pragma unroll
            for (int ng = 0; ng < 4; ng++) {
                u32 va = bufb + KV_V + (u32)(kt * 16 + vb_key) * ROWB + (u32)ng * 32 + vb_db;
                u32 vf[4];
                ldsm4t(vf, va);
                mma16816(oacc[2 * ng + 0], ap, &vf[0]);
                mma16816(oacc[2 * ng + 1], ap, &vf[2]);
            }
        }

        CP_WAIT0();
        __syncthreads();
    }

    // ---- write O (fp16) ----
    const float inv_lo = 1.f / l_lo, inv_hi = 1.f / l_hi;
    const int r_lo = q0 + (wid << 4) + (lid >> 2);
    const int cb = h * 64 + (lid & 3) * 2;
    #pragma unroll
    for (int j = 0; j < 8; j++) {
        int col = cb + j * 8;
        *reinterpret_cast<u32*>(oat + (size_t)(b * Nn + r_lo) * Dd + col) =
            h2pack(oacc[j][0] * inv_lo, oacc[j][1] * inv_lo);
        *reinterpret_cast<u32*>(oat + (size_t)(b * Nn + r_lo + 8) * Dd + col) =
            h2pack(oacc[j][2] * inv_hi, oacc[j][3] * inv_hi);
    }
}

// ============================================================
// FUSED: LayerNorm -> GELU -> comp -> outer -> top-51 -> write
// (R10-passing, unchanged)
// ============================================================
__global__ __launch_bounds__(512) void ln_outer_topk_kernel(
    const float* __restrict__ hsrc,
    const float* __restrict__ ln_g, const float* __restrict__ ln_b,
    const float* __restrict__ w2,  const float* __restrict__ b2,
    const float* __restrict__ F, const float* __restrict__ templates,
    float* __restrict__ out)
{
    __shared__ float s[512];
    __shared__ float Frow[512];
    __shared__ float red[32];
    __shared__ float cs[16];
    __shared__ float Qout[512 * 17];

    const int row = blockIdx.x;
    const int tid = threadIdx.x;
    const int m = tid >> 5, lid = tid & 31;

    float x = hsrc[(size_t)row * 512 + tid];
    s[tid] = x;
    Frow[tid] = F[(size_t)row * 512 + tid];

    float sum = x, sq = x * x;
    #pragma unroll
    for (int o = 16; o >= 1; o >>= 1) {
        sum += __shfl_xor_sync(0xffffffffu, sum, o);
        sq  += __shfl_xor_sync(0xffffffffu, sq,  o);
    }
    if (lid == 0) { red[m] = sum; red[m + 16] = sq; }
    __syncthreads();
    if (tid == 0) {
        float S = 0.f, Q = 0.f;
        #pragma unroll
        for (int i = 0; i < 16; i++) { S += red[i]; Q += red[i + 16]; }
        red[0] = S * (1.f / 512.f);
        red[16] = Q * (1.f / 512.f);
    }
    __syncthreads();
    const float mean = red[0];
    const float rstd = rsqrtf(red[16] - mean * mean + 1e-5f);

    float g = (x - mean) * rstd * ln_g[tid] + ln_b[tid];
    g = 0.5f * g * (1.f + erff(g * 0.70710678118f));
    __syncthreads();
    s[tid] = g;
    __syncthreads();

    {
        float p = 0.f;
        const float* wrow = w2 + m * 512;
        #pragma unroll
        for (int i = 0; i < 16; i++) {
            int e = lid + 32 * i;
            p += s[e] * wrow[e];
        }
        #pragma unroll
        for (int o = 16; o >= 1; o >>= 1)
            p += __shfl_xor_sync(0xffffffffu, p, o);
        if (lid == 0) cs[m] = p + b2[m];
    }
    __syncthreads();

    const float c = cs[m];
    float    qv[16];
    unsigned key[16];
    unsigned mx = 0;
    #pragma unroll
    for (int i = 0; i < 16; i++) {
        int d = lid + 32 * i;
        float q = Frow[d] * templates[m * 512 + d] * c;
        qv[i]  = q;
        key[i] = __float_as_uint(fabsf(q));
        mx = max(mx, key[i]);
    }
    #pragma unroll
    for (int o = 16; o >= 1; o >>= 1)
        mx = max(mx, __shfl_xor_sync(0xffffffffu, mx, o));

    unsigned prefix = 0;
    int bit = 31 - __clz(mx | 1u);
    for (; bit >= 0; bit--) {
        unsigned test = prefix | (1u << bit);
        int cnt = 0;
        #pragma unroll
        for (int i = 0; i < 16; i++) cnt += (key[i] >= test);
        cnt = __reduce_add_sync(0xffffffffu, cnt);
        if (cnt >= KTOP) {
            prefix = test;
            if (cnt == KTOP) break;
        }
    }

    #pragma unroll
    for (int i = 0; i < 16; i++) {
        int d = lid + 32 * i;
        Qout[d * 17 + m] = (key[i] >= prefix) ? qv[i] : 0.f;
    }
    __syncthreads();

    float* ob = out + (size_t)row * (512 * 16);
    #pragma unroll
    for (int i = 0; i < 16; i++) {
        int e = tid + 512 * i;
        ob[e] = Qout[(e >> 4) * 17 + (e & 15)];
    }
}

// ============================================================
extern "C" void kernel_launch(void* const* d_in, const int* in_sizes, int n_in,
                              void* d_out, int out_size) {
    const float* F    = (const float*)d_in[0];
    const float* Wqkv = (const float*)d_in[1];
    const float* bqkv = (const float*)d_in[2];
    const float* Wout = (const float*)d_in[3];
    const float* bout = (const float*)d_in[4];
    const float* w1   = (const float*)d_in[5];
    const float* b1   = (const float*)d_in[6];
    const float* lng  = (const float*)d_in[7];
    const float* lnb  = (const float*)d_in[8];
    const float* w2   = (const float*)d_in[9];
    const float* b2   = (const float*)d_in[10];
    const float* tmpl = (const float*)d_in[11];
    float* out = (float*)d_out;

    __half *qkv16, *F16, *wq, *wo, *w1h, *at16, *fe16;
    float *hbuf;
    cudaGetSymbolAddress((void**)&qkv16, g_qkv);
    cudaGetSymbolAddress((void**)&F16,   g_F16);
    cudaGetSymbolAddress((void**)&wq,    g_wq);
    cudaGetSymbolAddress((void**)&wo,    g_wo);
    cudaGetSymbolAddress((void**)&w1h,   g_w1);
    cudaGetSymbolAddress((void**)&at16,  g_at);
    cudaGetSymbolAddress((void**)&fe16,  g_fe);
    cudaGetSymbolAddress((void**)&hbuf,  g_h);

    cudaFuncSetAttribute(sgemm_tc, cudaFuncAttributeMaxDynamicSharedMemorySize,
                         GEMM_SMEM);
    cudaFuncSetAttribute(attn_tc, cudaFuncAttributeMaxDynamicSharedMemorySize,
                         ATTN_SMEM);

    // fp32 -> fp16 convert (one launch)
    cvt_all_kernel<<<(SEG3 + 255) / 256, 256>>>(F, Wqkv, Wout, w1, F16, wq, wo, w1h);

    // qkv = F @ Wqkv^T + bqkv -> fp16 (Q scaled 1/8)
    sgemm_tc<<<dim3(1536 / 128, BN / 128), 512, GEMM_SMEM>>>(
        F16, wq, bqkv, nullptr, nullptr, qkv16, 1, 512, 1536);
    // attention -> fp16 O
    attn_tc<<<dim3(Nn / QT, Bb * Hh), 192, ATTN_SMEM>>>(qkv16, at16);
    // fenh = F + O @ Wout^T + bout -> fp16
    sgemm_tc<<<dim3(512 / 128, BN / 128), 512, GEMM_SMEM>>>(
        at16, wo, bout, F, nullptr, fe16, 0, 512, 512);
    // h = fenh @ w1^T + b1 -> fp32
    sgemm_tc<<<dim3(512 / 128, BN / 128), 512, GEMM_SMEM>>>(
        fe16, w1h, b1, nullptr, hbuf, nullptr, 0, 512, 512);
    // fused LN -> GELU -> comp -> outer -> topk -> write
    ln_outer_topk_kernel<<<BN, 512>>>(hbuf, lng, lnb, w2, b2, F, tmpl, out);
}